// round 3
// baseline (speedup 1.0000x reference)
#include <cuda_runtime.h>
#include <cstdint>

#define NN 100000
#define NE 1600000
#define KIN 128
#define HID 128
#define DOUT 64
#define EDIM 16

// ---------------- device scratch (no allocations allowed) ----------------
__device__ float g_featA[NN * HID];   // post-GEMM features (conv1/2: 128-wide; mu|ls interleaved)
__device__ float g_acc[NN * HID];     // aggregation accumulator
__device__ float g_nodeB[NN * HID];   // node features between convs
__device__ float g_res[NN * HID];     // residual x@Wr+br
__device__ float g_as[NN], g_ad[NN];      // attention dots (conv1/2, mu)
__device__ float g_as2[NN], g_ad2[NN];    // attention dots (ls)
__device__ float g_denom[NN], g_selfexp[NN];    // mu / generic
__device__ float g_denom2[NN], g_selfexp2[NN];  // ls
__device__ float g_expl[NE];   // mu / generic
__device__ float g_expl2[NE];  // ls
__device__ float g_et2[NE], g_etMu[NE], g_etLs[NE];
__device__ float g_s2[NN], g_sMu[NN], g_sLs[NN];
__device__ int   g_cnt[NN];
__device__ float g_we[48];

// ---------------- small helper kernels ----------------

// we[m][j] = dot(We_m[j,:], ae_m)   (3 matrices, 16 rows each)
__global__ void we_kernel(const float* __restrict__ We2, const float* __restrict__ ae2,
                          const float* __restrict__ Wemu, const float* __restrict__ aemu,
                          const float* __restrict__ Wels, const float* __restrict__ aels) {
    int t = threadIdx.x;
    if (t >= 48) return;
    int m = t >> 4, j = t & 15;
    float s = 0.f;
    if (m == 0) { for (int c = 0; c < HID; c++)  s += We2[j * HID + c]  * ae2[c]; }
    else if (m == 1) { for (int c = 0; c < DOUT; c++) s += Wemu[j * DOUT + c] * aemu[c]; }
    else { for (int c = 0; c < DOUT; c++) s += Wels[j * DOUT + c] * aels[c]; }
    g_we[t] = s;
}

__global__ void zero_init_kernel() {
    int i = blockIdx.x * blockDim.x + threadIdx.x;
    if (i >= NN) return;
    g_cnt[i] = 0; g_s2[i] = 0.f; g_sMu[i] = 0.f; g_sLs[i] = 0.f;
}

// zero acc[N*128] and denom(s)
template <bool DUAL>
__global__ void zero_conv_kernel() {
    int idx4 = blockIdx.x * blockDim.x + threadIdx.x;
    if (idx4 < NN * 128 / 4) {
        *(float4*)&g_acc[idx4 * 4] = make_float4(0.f, 0.f, 0.f, 0.f);
    }
    if (idx4 < NN / 4) {
        *(float4*)&g_denom[idx4 * 4] = make_float4(0.f, 0.f, 0.f, 0.f);
        if (DUAL) *(float4*)&g_denom2[idx4 * 4] = make_float4(0.f, 0.f, 0.f, 0.f);
    }
}

// per-edge scalar attr terms for all three attr convs + per-dst sums & counts
__global__ void eterm_kernel(const float* __restrict__ ea, const int* __restrict__ ei) {
    __shared__ float swe[48];
    if (threadIdx.x < 48) swe[threadIdx.x] = g_we[threadIdx.x];
    __syncthreads();
    int e = blockIdx.x * blockDim.x + threadIdx.x;
    if (e >= NE) return;
    const float4* p = (const float4*)(ea + (size_t)e * EDIM);
    float v[16];
    float4 q0 = p[0], q1 = p[1], q2 = p[2], q3 = p[3];
    v[0]=q0.x; v[1]=q0.y; v[2]=q0.z; v[3]=q0.w;
    v[4]=q1.x; v[5]=q1.y; v[6]=q1.z; v[7]=q1.w;
    v[8]=q2.x; v[9]=q2.y; v[10]=q2.z; v[11]=q2.w;
    v[12]=q3.x; v[13]=q3.y; v[14]=q3.z; v[15]=q3.w;
    float t2 = 0.f, tm = 0.f, tl = 0.f;
#pragma unroll
    for (int j = 0; j < 16; j++) {
        t2 += v[j] * swe[j];
        tm += v[j] * swe[16 + j];
        tl += v[j] * swe[32 + j];
    }
    g_et2[e] = t2; g_etMu[e] = tm; g_etLs[e] = tl;
    int d = ei[NE + e];
    atomicAdd(&g_s2[d], t2);
    atomicAdd(&g_sMu[d], tm);
    atomicAdd(&g_sLs[d], tl);
    atomicAdd(&g_cnt[d], 1);
}

// ---------------- GEMM: C[nrows,BN] = A[nrows,128] @ W[128,BN] (+bias), C row stride ldc ----------------
template <int BN>
__global__ void __launch_bounds__(256) gemm_kernel(const float* __restrict__ A,
                                                   const float* __restrict__ W,
                                                   const float* __restrict__ bias,
                                                   float* __restrict__ C, int nrows, int ldc) {
    constexpr int BM = 64, BK = 32, K = 128;
    constexpr int TN = BN / 32;
    __shared__ float As[BK][BM];
    __shared__ float Ws[BK * BN];
    int tid = threadIdx.x;
    int row0 = blockIdx.x * BM;
    int trow = tid >> 5, lane = tid & 31;

    float acc[8][TN];
#pragma unroll
    for (int i = 0; i < 8; i++)
#pragma unroll
        for (int j = 0; j < TN; j++) acc[i][j] = 0.f;

    for (int k0 = 0; k0 < K; k0 += BK) {
        int r = tid >> 2, kq = (tid & 3) * 8;
        int grow = row0 + r;
        float4 a0, a1;
        if (grow < nrows) {
            a0 = *(const float4*)(A + (size_t)grow * K + k0 + kq);
            a1 = *(const float4*)(A + (size_t)grow * K + k0 + kq + 4);
        } else {
            a0 = make_float4(0, 0, 0, 0); a1 = a0;
        }
        As[kq + 0][r] = a0.x; As[kq + 1][r] = a0.y; As[kq + 2][r] = a0.z; As[kq + 3][r] = a0.w;
        As[kq + 4][r] = a1.x; As[kq + 5][r] = a1.y; As[kq + 6][r] = a1.z; As[kq + 7][r] = a1.w;
        constexpr int WL = (BK * BN / 4) / 256;
        const float4* Wg = (const float4*)(W + (size_t)k0 * BN);
        float4* Wsv = (float4*)Ws;
#pragma unroll
        for (int u = 0; u < WL; u++) Wsv[tid + u * 256] = Wg[tid + u * 256];
        __syncthreads();
#pragma unroll
        for (int kk = 0; kk < BK; kk++) {
            float4 av0 = *(const float4*)&As[kk][trow * 8];
            float4 av1 = *(const float4*)&As[kk][trow * 8 + 4];
            float a[8] = {av0.x, av0.y, av0.z, av0.w, av1.x, av1.y, av1.z, av1.w};
            float b[TN];
            if (TN == 4) {
                float4 bv = *(const float4*)&Ws[kk * BN + lane * 4];
                b[0] = bv.x; b[1] = bv.y; b[2] = bv.z; b[3] = bv.w;
            } else {
                float2 bv = *(const float2*)&Ws[kk * BN + lane * 2];
                b[0] = bv.x; b[1] = bv.y;
            }
#pragma unroll
            for (int i = 0; i < 8; i++)
#pragma unroll
                for (int j = 0; j < TN; j++) acc[i][j] += a[i] * b[j];
        }
        __syncthreads();
    }

#pragma unroll
    for (int i = 0; i < 8; i++) {
        int grow = row0 + trow * 8 + i;
        if (grow >= nrows) continue;
        int col = lane * TN;
        if (TN == 4) {
            float4 v = make_float4(acc[i][0], acc[i][1], acc[i][2], acc[i][3]);
            if (bias) { v.x += bias[col]; v.y += bias[col + 1]; v.z += bias[col + 2]; v.w += bias[col + 3]; }
            *(float4*)(C + (size_t)grow * ldc + col) = v;
        } else {
            float2 v = make_float2(acc[i][0], acc[i][1]);
            if (bias) { v.x += bias[col]; v.y += bias[col + 1]; }
            *(float2*)(C + (size_t)grow * ldc + col) = v;
        }
    }
}

// ---------------- per-node attention dots ----------------
// C = active feature width; STRIDE = row stride of feat
template <int C, int STRIDE>
__global__ void dots_kernel(const float* __restrict__ feat,
                            const float* __restrict__ asrc,
                            const float* __restrict__ adst,
                            float* __restrict__ oS, float* __restrict__ oD) {
    int warp = (blockIdx.x * blockDim.x + threadIdx.x) >> 5;
    int lane = threadIdx.x & 31;
    if (warp >= NN) return;
    float ps = 0.f, pd = 0.f;
    if (C == 128) {
        float4 v = *(const float4*)(feat + (size_t)warp * STRIDE + lane * 4);
        float4 s = *(const float4*)(asrc + lane * 4);
        float4 d = *(const float4*)(adst + lane * 4);
        ps = v.x * s.x + v.y * s.y + v.z * s.z + v.w * s.w;
        pd = v.x * d.x + v.y * d.y + v.z * d.z + v.w * d.w;
    } else {
        float2 v = *(const float2*)(feat + (size_t)warp * STRIDE + lane * 2);
        float2 s = *(const float2*)(asrc + lane * 2);
        float2 d = *(const float2*)(adst + lane * 2);
        ps = v.x * s.x + v.y * s.y;
        pd = v.x * d.x + v.y * d.y;
    }
#pragma unroll
    for (int off = 16; off; off >>= 1) {
        ps += __shfl_xor_sync(0xffffffffu, ps, off);
        pd += __shfl_xor_sync(0xffffffffu, pd, off);
    }
    if (lane == 0) { oS[warp] = ps; oD[warp] = pd; }
}

// ---------------- edge logits -> exp -> denom ----------------
template <bool HASE>
__global__ void p1_kernel(const int* __restrict__ ei, const float* __restrict__ et) {
    int e = blockIdx.x * blockDim.x + threadIdx.x;
    if (e >= NE) return;
    int s = ei[e], d = ei[NE + e];
    float l = g_as[s] + g_ad[d];
    if (HASE) l += et[e];
    l = l > 0.f ? l : 0.2f * l;
    float ex = expf(l);
    g_expl[e] = ex;
    atomicAdd(&g_denom[d], ex);
}

// dual: mu (as/ad/etMu -> expl/denom) and ls (as2/ad2/etLs -> expl2/denom2)
__global__ void p1_dual_kernel(const int* __restrict__ ei) {
    int e = blockIdx.x * blockDim.x + threadIdx.x;
    if (e >= NE) return;
    int s = ei[e], d = ei[NE + e];
    float lm = g_as[s] + g_ad[d] + g_etMu[e];
    float ll = g_as2[s] + g_ad2[d] + g_etLs[e];
    lm = lm > 0.f ? lm : 0.2f * lm;
    ll = ll > 0.f ? ll : 0.2f * ll;
    float em = expf(lm), el = expf(ll);
    g_expl[e] = em; g_expl2[e] = el;
    atomicAdd(&g_denom[d], em);
    atomicAdd(&g_denom2[d], el);
}

template <bool HASE>
__global__ void self_kernel(const float* __restrict__ sArr) {
    int i = blockIdx.x * blockDim.x + threadIdx.x;
    if (i >= NN) return;
    float etv = 0.f;
    if (HASE) etv = sArr[i] / fmaxf((float)g_cnt[i], 1.f);
    float l = g_as[i] + g_ad[i] + etv;
    l = l > 0.f ? l : 0.2f * l;
    float ex = expf(l);
    g_selfexp[i] = ex;
    g_denom[i] += ex;  // runs after p1 (stream-ordered), unique i
}

__global__ void self_dual_kernel() {
    int i = blockIdx.x * blockDim.x + threadIdx.x;
    if (i >= NN) return;
    float inv = 1.f / fmaxf((float)g_cnt[i], 1.f);
    float lm = g_as[i] + g_ad[i] + g_sMu[i] * inv;
    float ll = g_as2[i] + g_ad2[i] + g_sLs[i] * inv;
    lm = lm > 0.f ? lm : 0.2f * lm;
    ll = ll > 0.f ? ll : 0.2f * ll;
    float em = expf(lm), el = expf(ll);
    g_selfexp[i] = em; g_selfexp2[i] = el;
    g_denom[i] += em;
    g_denom2[i] += el;
}

// ---------------- weighted scatter-add (128-wide rows) ----------------
// DUAL: lanes 0-15 use mu coef (cols 0-63), lanes 16-31 use ls coef (cols 64-127)
template <bool DUAL>
__global__ void __launch_bounds__(256) scatter_kernel(const int* __restrict__ ei,
                                                      const float* __restrict__ feat,
                                                      float* __restrict__ acc) {
    int gt = blockIdx.x * 256 + threadIdx.x;
    int e = gt >> 5;
    int lane = gt & 31;
    if (e >= NE) return;
    int s = ei[e], d = ei[NE + e];
    float coef;
    if (DUAL) {
        coef = (lane < 16) ? (g_expl[e] / (g_denom[d] + 1e-16f))
                           : (g_expl2[e] / (g_denom2[d] + 1e-16f));
    } else {
        coef = g_expl[e] / (g_denom[d] + 1e-16f);
    }
    float4 v = *(const float4*)(feat + (size_t)s * 128 + lane * 4);
    float* p = acc + (size_t)d * 128 + lane * 4;
    asm volatile("red.global.add.v4.f32 [%0], {%1,%2,%3,%4};"
                 :: "l"(p), "f"(coef * v.x), "f"(coef * v.y), "f"(coef * v.z), "f"(coef * v.w)
                 : "memory");
}

// ---------------- finalize: out = act(acc + selfcoef*feat + b [+ res]) ----------------
// MODE 0: relu   MODE 1: relu + res
template <int MODE>
__global__ void finalize_kernel(const float* __restrict__ feat,
                                const float* __restrict__ bias,
                                const float* __restrict__ res,
                                float* __restrict__ out) {
    int idx4 = blockIdx.x * blockDim.x + threadIdx.x;
    if (idx4 >= NN * 128 / 4) return;
    int i = idx4 >> 5;
    int c4 = (idx4 & 31) * 4;
    float coef = g_selfexp[i] / (g_denom[i] + 1e-16f);
    float4 a = *(const float4*)(g_acc + (size_t)i * 128 + c4);
    float4 f = *(const float4*)(feat + (size_t)i * 128 + c4);
    float4 b = *(const float4*)(bias + c4);
    float4 v;
    v.x = a.x + coef * f.x + b.x;
    v.y = a.y + coef * f.y + b.y;
    v.z = a.z + coef * f.z + b.z;
    v.w = a.w + coef * f.w + b.w;
    v.x = fmaxf(v.x, 0.f); v.y = fmaxf(v.y, 0.f);
    v.z = fmaxf(v.z, 0.f); v.w = fmaxf(v.w, 0.f);
    if (MODE == 1) {
        float4 r = *(const float4*)(res + (size_t)i * 128 + c4);
        v.x += r.x; v.y += r.y; v.z += r.z; v.w += r.w;
    }
    *(float4*)(out + (size_t)i * 128 + c4) = v;
}

// dual finalize: cols 0-63 -> out_mu (coef mu, bias bmu), cols 64-127 -> out_ls
__global__ void finalize_dual_kernel(const float* __restrict__ feat,
                                     const float* __restrict__ bmu,
                                     const float* __restrict__ bls,
                                     float* __restrict__ out_mu,
                                     float* __restrict__ out_ls) {
    int idx4 = blockIdx.x * blockDim.x + threadIdx.x;
    if (idx4 >= NN * 128 / 4) return;
    int i = idx4 >> 5;
    int c4 = (idx4 & 31) * 4;
    bool isMu = c4 < 64;
    float coef = isMu ? (g_selfexp[i] / (g_denom[i] + 1e-16f))
                      : (g_selfexp2[i] / (g_denom2[i] + 1e-16f));
    float4 a = *(const float4*)(g_acc + (size_t)i * 128 + c4);
    float4 f = *(const float4*)(feat + (size_t)i * 128 + c4);
    int cc = isMu ? c4 : (c4 - 64);
    float4 b = isMu ? *(const float4*)(bmu + cc) : *(const float4*)(bls + cc);
    float4 v;
    v.x = a.x + coef * f.x + b.x;
    v.y = a.y + coef * f.y + b.y;
    v.z = a.z + coef * f.z + b.z;
    v.w = a.w + coef * f.w + b.w;
    float* out = isMu ? (out_mu + (size_t)i * 64 + cc) : (out_ls + (size_t)i * 64 + cc);
    *(float4*)out = v;
}

// ---------------- host orchestration ----------------
extern "C" void kernel_launch(void* const* d_in, const int* in_sizes, int n_in,
                              void* d_out, int out_size) {
    const float* x   = (const float*)d_in[0];
    const int*   ei  = (const int*)d_in[1];
    const float* ea  = (const float*)d_in[2];
    const float* W1  = (const float*)d_in[3];
    const float* a1s = (const float*)d_in[4];
    const float* a1d = (const float*)d_in[5];
    const float* b1  = (const float*)d_in[6];
    const float* W2  = (const float*)d_in[7];
    const float* a2s = (const float*)d_in[8];
    const float* a2d = (const float*)d_in[9];
    const float* b2  = (const float*)d_in[10];
    const float* We2 = (const float*)d_in[11];
    const float* ae2 = (const float*)d_in[12];
    const float* Wr  = (const float*)d_in[13];
    const float* br  = (const float*)d_in[14];
    const float* Wmu = (const float*)d_in[15];
    const float* ams = (const float*)d_in[16];
    const float* amd = (const float*)d_in[17];
    const float* bmu = (const float*)d_in[18];
    const float* Wem = (const float*)d_in[19];
    const float* aem = (const float*)d_in[20];
    const float* Wls = (const float*)d_in[21];
    const float* als = (const float*)d_in[22];
    const float* ald = (const float*)d_in[23];
    const float* bls = (const float*)d_in[24];
    const float* Wel = (const float*)d_in[25];
    const float* ael = (const float*)d_in[26];

    float* out_mu = (float*)d_out;
    float* out_ls = out_mu + (size_t)NN * DOUT;

    void *pFeat, *pAcc, *pNodeB, *pRes, *pEt2, *pS2, *pAs, *pAd, *pAs2, *pAd2;
    cudaGetSymbolAddress(&pFeat, g_featA);
    cudaGetSymbolAddress(&pAcc, g_acc);
    cudaGetSymbolAddress(&pNodeB, g_nodeB);
    cudaGetSymbolAddress(&pRes, g_res);
    cudaGetSymbolAddress(&pEt2, g_et2);
    cudaGetSymbolAddress(&pS2, g_s2);
    cudaGetSymbolAddress(&pAs, g_as);
    cudaGetSymbolAddress(&pAd, g_ad);
    cudaGetSymbolAddress(&pAs2, g_as2);
    cudaGetSymbolAddress(&pAd2, g_ad2);
    float* featA = (float*)pFeat;
    float* accP  = (float*)pAcc;
    float* nodeB = (float*)pNodeB;
    float* resP  = (float*)pRes;

    const int TB = 256;
    int nbN   = (NN + TB - 1) / TB;
    int nbE   = (NE + TB - 1) / TB;
    int nbDot = (NN * 32 + TB - 1) / TB;
    int nbG   = (NN + 63) / 64;
    int nbZ128 = (NN * 128 / 4 + TB - 1) / TB;
    int nbSc  = NE / 8;   // 1 warp per edge, 256 threads/block

    // ---- setup ----
    zero_init_kernel<<<nbN, TB>>>();
    we_kernel<<<1, 64>>>(We2, ae2, Wem, aem, Wel, ael);
    eterm_kernel<<<nbE, TB>>>(ea, ei);

    // residual (independent)
    gemm_kernel<128><<<nbG, TB>>>(x, Wr, br, resP, NN, 128);

    // ---- conv1 (no edge attr) ----
    gemm_kernel<128><<<nbG, TB>>>(x, W1, nullptr, featA, NN, 128);
    dots_kernel<128, 128><<<nbDot, TB>>>(featA, a1s, a1d, (float*)pAs, (float*)pAd);
    zero_conv_kernel<false><<<nbZ128, TB>>>();
    p1_kernel<false><<<nbE, TB>>>(ei, nullptr);
    self_kernel<false><<<nbN, TB>>>(nullptr);
    scatter_kernel<false><<<nbSc, TB>>>(ei, featA, accP);
    finalize_kernel<0><<<nbZ128, TB>>>(featA, b1, nullptr, nodeB);

    // ---- conv2 (edge attr) ----
    gemm_kernel<128><<<nbG, TB>>>(nodeB, W2, nullptr, featA, NN, 128);
    dots_kernel<128, 128><<<nbDot, TB>>>(featA, a2s, a2d, (float*)pAs, (float*)pAd);
    zero_conv_kernel<false><<<nbZ128, TB>>>();
    p1_kernel<true><<<nbE, TB>>>(ei, (const float*)pEt2);
    self_kernel<true><<<nbN, TB>>>((const float*)pS2);
    scatter_kernel<false><<<nbSc, TB>>>(ei, featA, accP);
    finalize_kernel<1><<<nbZ128, TB>>>(featA, b2, resP, nodeB);  // nodeB = h

    // ---- conv_mu + conv_logstd fused (interleaved [mu(64)|ls(64)] rows) ----
    gemm_kernel<64><<<nbG, TB>>>(nodeB, Wmu, nullptr, featA, NN, 128);       // cols 0-63
    gemm_kernel<64><<<nbG, TB>>>(nodeB, Wls, nullptr, featA + 64, NN, 128);  // cols 64-127
    dots_kernel<64, 128><<<nbDot, TB>>>(featA, ams, amd, (float*)pAs, (float*)pAd);
    dots_kernel<64, 128><<<nbDot, TB>>>(featA + 64, als, ald, (float*)pAs2, (float*)pAd2);
    zero_conv_kernel<true><<<nbZ128, TB>>>();
    p1_dual_kernel<<<nbE, TB>>>(ei);
    self_dual_kernel<<<nbN, TB>>>();
    scatter_kernel<true><<<nbSc, TB>>>(ei, featA, accP);
    finalize_dual_kernel<<<nbZ128, TB>>>(featA, bmu, bls, out_mu, out_ls);

    (void)in_sizes; (void)n_in; (void)out_size;
}

// round 12
// speedup vs baseline: 1.6655x; 1.6655x over previous
#include <cuda_runtime.h>
#include <cstdint>

#define NN 100000
#define NE 1600000
#define HID 128
#define DOUT 64
#define EDIM 16

// ---------------- device scratch ----------------
__device__ float g_featA[NN * HID];   // post-GEMM features (conv1/2: 128-wide; mu|ls interleaved)
__device__ float g_nodeB[NN * HID];   // node features between convs
__device__ float g_res[NN * HID];     // residual x@Wr+br
__device__ float g_as[NN], g_ad[NN];      // attention dots (conv1/2, mu)
__device__ float g_as2[NN], g_ad2[NN];    // attention dots (ls)
__device__ int   g_cnt[NN];
__device__ int   g_cursor[NN];
__device__ int   g_rowstart[NN + 1];
__device__ float4 g_csr[NE];          // {src_as_float, et2, etMu, etLs} sorted by dst
__device__ float g_we[48];

// ---------------- setup kernels ----------------

__global__ void __launch_bounds__(64) we_kernel(
                          const float* __restrict__ We2, const float* __restrict__ ae2,
                          const float* __restrict__ Wemu, const float* __restrict__ aemu,
                          const float* __restrict__ Wels, const float* __restrict__ aels) {
    int t = threadIdx.x;
    if (t >= 48) return;
    int m = t >> 4, j = t & 15;
    float s = 0.f;
    if (m == 0) { for (int c = 0; c < HID; c++)  s += We2[j * HID + c]  * ae2[c]; }
    else if (m == 1) { for (int c = 0; c < DOUT; c++) s += Wemu[j * DOUT + c] * aemu[c]; }
    else { for (int c = 0; c < DOUT; c++) s += Wels[j * DOUT + c] * aels[c]; }
    g_we[t] = s;
}

__global__ void __launch_bounds__(256) zero_cnt_kernel() {
    int i = blockIdx.x * blockDim.x + threadIdx.x;
    if (i >= NN) return;
    g_cnt[i] = 0; g_cursor[i] = 0;
}

__global__ void __launch_bounds__(256) count_kernel(const int* __restrict__ ei) {
    int e = blockIdx.x * blockDim.x + threadIdx.x;
    if (e >= NE) return;
    atomicAdd(&g_cnt[ei[NE + e]], 1);
}

// single-block exclusive scan of g_cnt -> g_rowstart
__global__ void __launch_bounds__(1024) scan_kernel() {
    __shared__ int part[1024];
    int t = threadIdx.x;
    const int CH = (NN + 1023) / 1024;  // 98
    int base = t * CH;
    int sum = 0;
#pragma unroll 1
    for (int k = 0; k < CH; k++) {
        int i = base + k;
        if (i < NN) sum += g_cnt[i];
    }
    part[t] = sum;
    __syncthreads();
#pragma unroll 1
    for (int off = 1; off < 1024; off <<= 1) {
        int v = (t >= off) ? part[t - off] : 0;
        __syncthreads();
        part[t] += v;
        __syncthreads();
    }
    int ex = (t == 0) ? 0 : part[t - 1];
#pragma unroll 1
    for (int k = 0; k < CH; k++) {
        int i = base + k;
        if (i < NN) { g_rowstart[i] = ex; ex += g_cnt[i]; }
    }
    if (t == 1023) g_rowstart[NN] = NE;
}

// per-edge: compute 3 edge-attr scalar terms, place into CSR slot by dst
__global__ void __launch_bounds__(256) place_kernel(const float* __restrict__ ea,
                                                    const int* __restrict__ ei) {
    __shared__ float swe[48];
    if (threadIdx.x < 48) swe[threadIdx.x] = g_we[threadIdx.x];
    __syncthreads();
    int e = blockIdx.x * blockDim.x + threadIdx.x;
    if (e >= NE) return;
    const float4* p = (const float4*)(ea + (size_t)e * EDIM);
    float4 q0 = p[0], q1 = p[1], q2 = p[2], q3 = p[3];
    float v[16] = {q0.x,q0.y,q0.z,q0.w, q1.x,q1.y,q1.z,q1.w,
                   q2.x,q2.y,q2.z,q2.w, q3.x,q3.y,q3.z,q3.w};
    float t2 = 0.f, tm = 0.f, tl = 0.f;
#pragma unroll
    for (int j = 0; j < 16; j++) {
        t2 += v[j] * swe[j];
        tm += v[j] * swe[16 + j];
        tl += v[j] * swe[32 + j];
    }
    int s = ei[e], d = ei[NE + e];
    int slot = g_rowstart[d] + atomicAdd(&g_cursor[d], 1);
    g_csr[slot] = make_float4(__int_as_float(s), t2, tm, tl);
}

// ---------------- GEMM: C[nrows,BN] = A[nrows,128] @ W[128,BN], C stride ldc ----------------
// optional fused attention dots: aS[row] = C_row . asrc, aD[row] = C_row . adst
template <int BN>
__global__ void __launch_bounds__(256) gemm_kernel(const float* __restrict__ A,
                                                   const float* __restrict__ W,
                                                   const float* __restrict__ bias,
                                                   float* __restrict__ C, int nrows, int ldc,
                                                   const float* __restrict__ asrc,
                                                   const float* __restrict__ adst,
                                                   float* __restrict__ aS,
                                                   float* __restrict__ aD) {
    constexpr int BM = 64, BK = 32, K = 128;
    constexpr int TN = BN / 32;
    __shared__ float As[BK][BM];
    __shared__ float Ws[BK * BN];
    int tid = threadIdx.x;
    int row0 = blockIdx.x * BM;
    int trow = tid >> 5, lane = tid & 31;

    float acc[8][TN];
#pragma unroll
    for (int i = 0; i < 8; i++)
#pragma unroll
        for (int j = 0; j < TN; j++) acc[i][j] = 0.f;

    for (int k0 = 0; k0 < K; k0 += BK) {
        int r = tid >> 2, kq = (tid & 3) * 8;
        int grow = row0 + r;
        float4 a0, a1;
        if (grow < nrows) {
            a0 = *(const float4*)(A + (size_t)grow * K + k0 + kq);
            a1 = *(const float4*)(A + (size_t)grow * K + k0 + kq + 4);
        } else {
            a0 = make_float4(0, 0, 0, 0); a1 = a0;
        }
        As[kq + 0][r] = a0.x; As[kq + 1][r] = a0.y; As[kq + 2][r] = a0.z; As[kq + 3][r] = a0.w;
        As[kq + 4][r] = a1.x; As[kq + 5][r] = a1.y; As[kq + 6][r] = a1.z; As[kq + 7][r] = a1.w;
        constexpr int WL = (BK * BN / 4) / 256;
        const float4* Wg = (const float4*)(W + (size_t)k0 * BN);
        float4* Wsv = (float4*)Ws;
#pragma unroll
        for (int u = 0; u < WL; u++) Wsv[tid + u * 256] = Wg[tid + u * 256];
        __syncthreads();
#pragma unroll
        for (int kk = 0; kk < BK; kk++) {
            float4 av0 = *(const float4*)&As[kk][trow * 8];
            float4 av1 = *(const float4*)&As[kk][trow * 8 + 4];
            float a[8] = {av0.x, av0.y, av0.z, av0.w, av1.x, av1.y, av1.z, av1.w};
            float b[TN];
            if (TN == 4) {
                float4 bv = *(const float4*)&Ws[kk * BN + lane * 4];
                b[0] = bv.x; b[1] = bv.y; b[2] = bv.z; b[3] = bv.w;
            } else {
                float2 bv = *(const float2*)&Ws[kk * BN + lane * 2];
                b[0] = bv.x; b[1] = bv.y;
            }
#pragma unroll
            for (int i = 0; i < 8; i++)
#pragma unroll
                for (int j = 0; j < TN; j++) acc[i][j] += a[i] * b[j];
        }
        __syncthreads();
    }

    float sA[TN], sD[TN];
    if (aS) {
#pragma unroll
        for (int j = 0; j < TN; j++) {
            sA[j] = asrc[lane * TN + j];
            sD[j] = adst[lane * TN + j];
        }
    }

#pragma unroll
    for (int i = 0; i < 8; i++) {
        int grow = row0 + trow * 8 + i;
        bool live = grow < nrows;
        int col = lane * TN;
        if (live) {
            if (TN == 4) {
                float4 v = make_float4(acc[i][0], acc[i][1], acc[i][2], acc[i][3]);
                if (bias) { v.x += bias[col]; v.y += bias[col + 1]; v.z += bias[col + 2]; v.w += bias[col + 3]; }
                *(float4*)(C + (size_t)grow * ldc + col) = v;
            } else {
                float2 v = make_float2(acc[i][0], acc[i][1]);
                if (bias) { v.x += bias[col]; v.y += bias[col + 1]; }
                *(float2*)(C + (size_t)grow * ldc + col) = v;
            }
        }
        if (aS) {
            float ps = 0.f, pd = 0.f;
#pragma unroll
            for (int j = 0; j < TN; j++) { ps += acc[i][j] * sA[j]; pd += acc[i][j] * sD[j]; }
#pragma unroll
            for (int off = 16; off; off >>= 1) {
                ps += __shfl_xor_sync(0xffffffffu, ps, off);
                pd += __shfl_xor_sync(0xffffffffu, pd, off);
            }
            if (lane == 0 && live) { aS[grow] = ps; aD[grow] = pd; }
        }
    }
}

// ---------------- fused gather: softmax-weighted aggregation per dst ----------------
// one warp per destination node; feat rows are 128-wide; software-pipelined
// MODE 0: relu   MODE 1: relu + res
template <bool HASE, int MODE>
__global__ void __launch_bounds__(256) gather_kernel(const float* __restrict__ feat,
                                                     const float* __restrict__ bias,
                                                     const float* __restrict__ res,
                                                     float* __restrict__ out) {
    int w = blockIdx.x * 8 + (threadIdx.x >> 5);
    int lane = threadIdx.x & 31;
    if (w >= NN) return;
    int start = g_rowstart[w], end = g_rowstart[w + 1];
    float adD = g_ad[w];
    float4 acc = make_float4(0.f, 0.f, 0.f, 0.f);
    float sumex = 0.f, sumet = 0.f;

    // software pipeline: prefetch csr entry + src attention dot one iter ahead
    float4 info;
    float asv = 0.f;
    if (start < end) {
        info = g_csr[start];
        asv = g_as[__float_as_int(info.x)];
    }
    for (int j = start; j < end; j++) {
        float4 cur = info;
        float asc = asv;
        if (j + 1 < end) {
            info = g_csr[j + 1];
            asv = g_as[__float_as_int(info.x)];
        }
        int s = __float_as_int(cur.x);
        float l = asc + adD;
        if (HASE) { l += cur.y; sumet += cur.y; }
        l = l > 0.f ? l : 0.2f * l;
        float ex = __expf(l);
        const float4 v = *(const float4*)(feat + (size_t)s * 128 + lane * 4);
        acc.x += ex * v.x; acc.y += ex * v.y; acc.z += ex * v.z; acc.w += ex * v.w;
        sumex += ex;
    }
    // self-loop (attr = per-dst mean of in-edge attrs)
    float etv = HASE ? (sumet / fmaxf((float)(end - start), 1.f)) : 0.f;
    float ls = g_as[w] + adD + etv;
    ls = ls > 0.f ? ls : 0.2f * ls;
    float exs = __expf(ls);
    const float4 vd = *(const float4*)(feat + (size_t)w * 128 + lane * 4);
    acc.x += exs * vd.x; acc.y += exs * vd.y; acc.z += exs * vd.z; acc.w += exs * vd.w;
    sumex += exs;
    float inv = 1.f / (sumex + 1e-16f);
    float4 b = *(const float4*)(bias + lane * 4);
    float4 o;
    o.x = acc.x * inv + b.x; o.y = acc.y * inv + b.y;
    o.z = acc.z * inv + b.z; o.w = acc.w * inv + b.w;
    o.x = fmaxf(o.x, 0.f); o.y = fmaxf(o.y, 0.f);
    o.z = fmaxf(o.z, 0.f); o.w = fmaxf(o.w, 0.f);
    if (MODE == 1) {
        float4 r = *(const float4*)(res + (size_t)w * 128 + lane * 4);
        o.x += r.x; o.y += r.y; o.z += r.z; o.w += r.w;
    }
    *(float4*)(out + (size_t)w * 128 + lane * 4) = o;
}

// dual gather: feat rows [mu(64)|ls(64)]; lanes 0-15 mu, 16-31 ls; no activation
__global__ void __launch_bounds__(256) gather_dual_kernel(const float* __restrict__ feat,
                                                          const float* __restrict__ bmu,
                                                          const float* __restrict__ bls,
                                                          float* __restrict__ out_mu,
                                                          float* __restrict__ out_ls) {
    int w = blockIdx.x * 8 + (threadIdx.x >> 5);
    int lane = threadIdx.x & 31;
    if (w >= NN) return;
    int half = lane >> 4;                 // 0 = mu, 1 = ls
    const float* asArr = half ? g_as2 : g_as;
    float adD = half ? g_ad2[w] : g_ad[w];
    int start = g_rowstart[w], end = g_rowstart[w + 1];
    float4 acc = make_float4(0.f, 0.f, 0.f, 0.f);
    float sumex = 0.f, sumet = 0.f;

    float4 info;
    float asv = 0.f;
    if (start < end) {
        info = g_csr[start];
        asv = asArr[__float_as_int(info.x)];
    }
    for (int j = start; j < end; j++) {
        float4 cur = info;
        float asc = asv;
        if (j + 1 < end) {
            info = g_csr[j + 1];
            asv = asArr[__float_as_int(info.x)];
        }
        int s = __float_as_int(cur.x);
        float et = half ? cur.w : cur.z;
        float l = asc + adD + et;
        sumet += et;
        l = l > 0.f ? l : 0.2f * l;
        float ex = __expf(l);
        const float4 v = *(const float4*)(feat + (size_t)s * 128 + lane * 4);
        acc.x += ex * v.x; acc.y += ex * v.y; acc.z += ex * v.z; acc.w += ex * v.w;
        sumex += ex;
    }
    float etv = sumet / fmaxf((float)(end - start), 1.f);
    float ls = asArr[w] + adD + etv;
    ls = ls > 0.f ? ls : 0.2f * ls;
    float exs = __expf(ls);
    const float4 vd = *(const float4*)(feat + (size_t)w * 128 + lane * 4);
    acc.x += exs * vd.x; acc.y += exs * vd.y; acc.z += exs * vd.z; acc.w += exs * vd.w;
    sumex += exs;
    float inv = 1.f / (sumex + 1e-16f);
    int cc = (lane & 15) * 4;
    const float* bp = half ? (bls + cc) : (bmu + cc);
    float4 b = *(const float4*)bp;
    float4 o;
    o.x = acc.x * inv + b.x; o.y = acc.y * inv + b.y;
    o.z = acc.z * inv + b.z; o.w = acc.w * inv + b.w;
    float* op = half ? (out_ls + (size_t)w * 64 + cc) : (out_mu + (size_t)w * 64 + cc);
    *(float4*)op = o;
}

// ---------------- host orchestration ----------------
extern "C" void kernel_launch(void* const* d_in, const int* in_sizes, int n_in,
                              void* d_out, int out_size) {
    const float* x   = (const float*)d_in[0];
    const int*   ei  = (const int*)d_in[1];
    const float* ea  = (const float*)d_in[2];
    const float* W1  = (const float*)d_in[3];
    const float* a1s = (const float*)d_in[4];
    const float* a1d = (const float*)d_in[5];
    const float* b1  = (const float*)d_in[6];
    const float* W2  = (const float*)d_in[7];
    const float* a2s = (const float*)d_in[8];
    const float* a2d = (const float*)d_in[9];
    const float* b2  = (const float*)d_in[10];
    const float* We2 = (const float*)d_in[11];
    const float* ae2 = (const float*)d_in[12];
    const float* Wr  = (const float*)d_in[13];
    const float* br  = (const float*)d_in[14];
    const float* Wmu = (const float*)d_in[15];
    const float* ams = (const float*)d_in[16];
    const float* amd = (const float*)d_in[17];
    const float* bmu = (const float*)d_in[18];
    const float* Wem = (const float*)d_in[19];
    const float* aem = (const float*)d_in[20];
    const float* Wls = (const float*)d_in[21];
    const float* als = (const float*)d_in[22];
    const float* ald = (const float*)d_in[23];
    const float* bls = (const float*)d_in[24];
    const float* Wel = (const float*)d_in[25];
    const float* ael = (const float*)d_in[26];

    float* out_mu = (float*)d_out;
    float* out_ls = out_mu + (size_t)NN * DOUT;

    void *pFeat, *pNodeB, *pRes, *pAs, *pAd, *pAs2, *pAd2;
    cudaGetSymbolAddress(&pFeat, g_featA);
    cudaGetSymbolAddress(&pNodeB, g_nodeB);
    cudaGetSymbolAddress(&pRes, g_res);
    cudaGetSymbolAddress(&pAs, g_as);
    cudaGetSymbolAddress(&pAd, g_ad);
    cudaGetSymbolAddress(&pAs2, g_as2);
    cudaGetSymbolAddress(&pAd2, g_ad2);
    float* featA = (float*)pFeat;
    float* nodeB = (float*)pNodeB;
    float* resP  = (float*)pRes;
    float* aS  = (float*)pAs;
    float* aD  = (float*)pAd;
    float* aS2 = (float*)pAs2;
    float* aD2 = (float*)pAd2;

    const int TB = 256;
    int nbN = (NN + TB - 1) / TB;
    int nbE = (NE + TB - 1) / TB;
    int nbG = (NN + 63) / 64;
    int nbW = (NN + 7) / 8;   // gather: warp per node

    // ---- CSR build + edge-attr scalar terms ----
    zero_cnt_kernel<<<nbN, TB>>>();
    we_kernel<<<1, 64>>>(We2, ae2, Wem, aem, Wel, ael);
    count_kernel<<<nbE, TB>>>(ei);
    scan_kernel<<<1, 1024>>>();
    place_kernel<<<nbE, TB>>>(ea, ei);

    // residual (independent of edge phase)
    gemm_kernel<128><<<nbG, TB>>>(x, Wr, br, resP, NN, 128, nullptr, nullptr, nullptr, nullptr);

    // ---- conv1 (no edge attr) ----
    gemm_kernel<128><<<nbG, TB>>>(x, W1, nullptr, featA, NN, 128, a1s, a1d, aS, aD);
    gather_kernel<false, 0><<<nbW, TB>>>(featA, b1, nullptr, nodeB);

    // ---- conv2 (edge attr) + residual ----
    gemm_kernel<128><<<nbG, TB>>>(nodeB, W2, nullptr, featA, NN, 128, a2s, a2d, aS, aD);
    gather_kernel<true, 1><<<nbW, TB>>>(featA, b2, resP, nodeB);   // nodeB = h

    // ---- conv_mu + conv_logstd fused (interleaved [mu|ls] rows) ----
    gemm_kernel<64><<<nbG, TB>>>(nodeB, Wmu, nullptr, featA, NN, 128, ams, amd, aS, aD);
    gemm_kernel<64><<<nbG, TB>>>(nodeB, Wls, nullptr, featA + 64, NN, 128, als, ald, aS2, aD2);
    gather_dual_kernel<<<nbW, TB>>>(featA, bmu, bls, out_mu, out_ls);

    (void)in_sizes; (void)n_in; (void)out_size;
}

// round 17
// speedup vs baseline: 1.8768x; 1.1268x over previous
#include <cuda_runtime.h>
#include <cstdint>

#define NN 100000
#define NE 1600000
#define HID 128
#define DOUT 64
#define EDIM 16

// ---------------- device scratch ----------------
__device__ float g_featA[NN * HID];   // post-GEMM features (conv1/2: 128-wide; mu|ls interleaved)
__device__ float g_nodeB[NN * HID];   // node features between convs
__device__ float g_res[NN * HID];     // residual x@Wr+br
__device__ float g_as[NN], g_ad[NN];      // attention dots (conv1/2, mu)
__device__ float g_as2[NN], g_ad2[NN];    // attention dots (ls)
__device__ __align__(16) int g_cnt[NN];
__device__ int   g_cursor[NN];
__device__ __align__(16) int g_rowstart[NN + 4];  // padded for int4 stores
__device__ float4 g_csr[NE];          // {src_as_float, et2, etMu, etLs} sorted by dst
__device__ float g_we[48];

// ---------------- setup kernels ----------------

__global__ void __launch_bounds__(64) we_kernel(
                          const float* __restrict__ We2, const float* __restrict__ ae2,
                          const float* __restrict__ Wemu, const float* __restrict__ aemu,
                          const float* __restrict__ Wels, const float* __restrict__ aels) {
    int t = threadIdx.x;
    if (t >= 48) return;
    int m = t >> 4, j = t & 15;
    float s = 0.f;
    if (m == 0) { for (int c = 0; c < HID; c++)  s += We2[j * HID + c]  * ae2[c]; }
    else if (m == 1) { for (int c = 0; c < DOUT; c++) s += Wemu[j * DOUT + c] * aemu[c]; }
    else { for (int c = 0; c < DOUT; c++) s += Wels[j * DOUT + c] * aels[c]; }
    g_we[t] = s;
}

__global__ void __launch_bounds__(256) zero_cnt_kernel() {
    int i = blockIdx.x * blockDim.x + threadIdx.x;
    if (i >= NN) return;
    g_cnt[i] = 0; g_cursor[i] = 0;
}

__global__ void __launch_bounds__(256) count_kernel(const int* __restrict__ ei) {
    int e = blockIdx.x * blockDim.x + threadIdx.x;
    if (e >= NE) return;
    atomicAdd(&g_cnt[ei[NE + e]], 1);
}

// single-block exclusive scan of g_cnt -> g_rowstart (vectorized int4, 100 ints/thread)
__global__ void __launch_bounds__(1024) scan_kernel() {
    __shared__ int part[1024];
    int t = threadIdx.x;
    const int C4 = 25;                 // int4 chunks per thread; threads 0..999 cover NN=100000
    const int N4 = NN / 4;             // 25000
    int base4 = t * C4;
    const int4* cnt4 = (const int4*)g_cnt;

    int sum = 0;
    if (base4 < N4) {
#pragma unroll 5
        for (int k = 0; k < C4; k++) {
            int4 c = cnt4[base4 + k];
            sum += c.x + c.y + c.z + c.w;
        }
    }
    part[t] = sum;
    __syncthreads();
#pragma unroll 1
    for (int off = 1; off < 1024; off <<= 1) {
        int v = (t >= off) ? part[t - off] : 0;
        __syncthreads();
        part[t] += v;
        __syncthreads();
    }
    int ex = (t == 0) ? 0 : part[t - 1];
    if (base4 < N4) {
        int4* rs4 = (int4*)g_rowstart;
#pragma unroll 5
        for (int k = 0; k < C4; k++) {
            int4 c = cnt4[base4 + k];
            int4 r;
            r.x = ex;
            r.y = r.x + c.x;
            r.z = r.y + c.y;
            r.w = r.z + c.z;
            ex = r.w + c.w;
            rs4[base4 + k] = r;
        }
    }
    if (t == 1023) g_rowstart[NN] = NE;
}

// per-edge: compute 3 edge-attr scalar terms, place into CSR slot by dst
__global__ void __launch_bounds__(256) place_kernel(const float* __restrict__ ea,
                                                    const int* __restrict__ ei) {
    __shared__ float swe[48];
    if (threadIdx.x < 48) swe[threadIdx.x] = g_we[threadIdx.x];
    __syncthreads();
    int e = blockIdx.x * blockDim.x + threadIdx.x;
    if (e >= NE) return;
    const float4* p = (const float4*)(ea + (size_t)e * EDIM);
    float4 q0 = p[0], q1 = p[1], q2 = p[2], q3 = p[3];
    float v[16] = {q0.x,q0.y,q0.z,q0.w, q1.x,q1.y,q1.z,q1.w,
                   q2.x,q2.y,q2.z,q2.w, q3.x,q3.y,q3.z,q3.w};
    float t2 = 0.f, tm = 0.f, tl = 0.f;
#pragma unroll
    for (int j = 0; j < 16; j++) {
        t2 += v[j] * swe[j];
        tm += v[j] * swe[16 + j];
        tl += v[j] * swe[32 + j];
    }
    int s = ei[e], d = ei[NE + e];
    int slot = g_rowstart[d] + atomicAdd(&g_cursor[d], 1);
    g_csr[slot] = make_float4(__int_as_float(s), t2, tm, tl);
}

// ---------------- GEMM: C[nrows,BN] = A[nrows,128] @ W[128,BN], C stride ldc ----------------
// optional fused attention dots: aS[row] = C_row . asrc, aD[row] = C_row . adst
template <int BN>
__global__ void __launch_bounds__(256) gemm_kernel(const float* __restrict__ A,
                                                   const float* __restrict__ W,
                                                   const float* __restrict__ bias,
                                                   float* __restrict__ C, int nrows, int ldc,
                                                   const float* __restrict__ asrc,
                                                   const float* __restrict__ adst,
                                                   float* __restrict__ aS,
                                                   float* __restrict__ aD) {
    constexpr int BM = 64, BK = 32, K = 128;
    constexpr int TN = BN / 32;
    __shared__ float As[BK][BM];
    __shared__ float Ws[BK * BN];
    int tid = threadIdx.x;
    int row0 = blockIdx.x * BM;
    int trow = tid >> 5, lane = tid & 31;

    float acc[8][TN];
#pragma unroll
    for (int i = 0; i < 8; i++)
#pragma unroll
        for (int j = 0; j < TN; j++) acc[i][j] = 0.f;

    for (int k0 = 0; k0 < K; k0 += BK) {
        int r = tid >> 2, kq = (tid & 3) * 8;
        int grow = row0 + r;
        float4 a0, a1;
        if (grow < nrows) {
            a0 = *(const float4*)(A + (size_t)grow * K + k0 + kq);
            a1 = *(const float4*)(A + (size_t)grow * K + k0 + kq + 4);
        } else {
            a0 = make_float4(0, 0, 0, 0); a1 = a0;
        }
        As[kq + 0][r] = a0.x; As[kq + 1][r] = a0.y; As[kq + 2][r] = a0.z; As[kq + 3][r] = a0.w;
        As[kq + 4][r] = a1.x; As[kq + 5][r] = a1.y; As[kq + 6][r] = a1.z; As[kq + 7][r] = a1.w;
        constexpr int WL = (BK * BN / 4) / 256;
        const float4* Wg = (const float4*)(W + (size_t)k0 * BN);
        float4* Wsv = (float4*)Ws;
#pragma unroll
        for (int u = 0; u < WL; u++) Wsv[tid + u * 256] = Wg[tid + u * 256];
        __syncthreads();
#pragma unroll
        for (int kk = 0; kk < BK; kk++) {
            float4 av0 = *(const float4*)&As[kk][trow * 8];
            float4 av1 = *(const float4*)&As[kk][trow * 8 + 4];
            float a[8] = {av0.x, av0.y, av0.z, av0.w, av1.x, av1.y, av1.z, av1.w};
            float b[TN];
            if (TN == 4) {
                float4 bv = *(const float4*)&Ws[kk * BN + lane * 4];
                b[0] = bv.x; b[1] = bv.y; b[2] = bv.z; b[3] = bv.w;
            } else {
                float2 bv = *(const float2*)&Ws[kk * BN + lane * 2];
                b[0] = bv.x; b[1] = bv.y;
            }
#pragma unroll
            for (int i = 0; i < 8; i++)
#pragma unroll
                for (int j = 0; j < TN; j++) acc[i][j] += a[i] * b[j];
        }
        __syncthreads();
    }

    float sA[TN], sD[TN];
    if (aS) {
#pragma unroll
        for (int j = 0; j < TN; j++) {
            sA[j] = asrc[lane * TN + j];
            sD[j] = adst[lane * TN + j];
        }
    }

#pragma unroll
    for (int i = 0; i < 8; i++) {
        int grow = row0 + trow * 8 + i;
        bool live = grow < nrows;
        int col = lane * TN;
        if (live) {
            if (TN == 4) {
                float4 v = make_float4(acc[i][0], acc[i][1], acc[i][2], acc[i][3]);
                if (bias) { v.x += bias[col]; v.y += bias[col + 1]; v.z += bias[col + 2]; v.w += bias[col + 3]; }
                *(float4*)(C + (size_t)grow * ldc + col) = v;
            } else {
                float2 v = make_float2(acc[i][0], acc[i][1]);
                if (bias) { v.x += bias[col]; v.y += bias[col + 1]; }
                *(float2*)(C + (size_t)grow * ldc + col) = v;
            }
        }
        if (aS) {
            float ps = 0.f, pd = 0.f;
#pragma unroll
            for (int j = 0; j < TN; j++) { ps += acc[i][j] * sA[j]; pd += acc[i][j] * sD[j]; }
#pragma unroll
            for (int off = 16; off; off >>= 1) {
                ps += __shfl_xor_sync(0xffffffffu, ps, off);
                pd += __shfl_xor_sync(0xffffffffu, pd, off);
            }
            if (lane == 0 && live) { aS[grow] = ps; aD[grow] = pd; }
        }
    }
}

// ---------------- fused dual GEMM: C[:, 0:64]=A@Wmu, C[:, 64:128]=A@Wls (ldc=128) ----------
// half-warp epilogue dots: lanes 0-15 -> mu (aS/aD), lanes 16-31 -> ls (aS2/aD2)
__global__ void __launch_bounds__(256) gemm_dual_kernel(const float* __restrict__ A,
                                                        const float* __restrict__ Wmu,
                                                        const float* __restrict__ Wls,
                                                        float* __restrict__ C, int nrows,
                                                        const float* __restrict__ ams,
                                                        const float* __restrict__ amd,
                                                        const float* __restrict__ als,
                                                        const float* __restrict__ ald,
                                                        float* __restrict__ aS,
                                                        float* __restrict__ aD,
                                                        float* __restrict__ aS2,
                                                        float* __restrict__ aD2) {
    constexpr int BM = 64, BK = 32, K = 128, BN = 128, TN = 4;
    __shared__ float As[BK][BM];
    __shared__ float Ws[BK * BN];
    int tid = threadIdx.x;
    int row0 = blockIdx.x * BM;
    int trow = tid >> 5, lane = tid & 31;

    float acc[8][TN];
#pragma unroll
    for (int i = 0; i < 8; i++)
#pragma unroll
        for (int j = 0; j < TN; j++) acc[i][j] = 0.f;

    for (int k0 = 0; k0 < K; k0 += BK) {
        int r = tid >> 2, kq = (tid & 3) * 8;
        int grow = row0 + r;
        float4 a0, a1;
        if (grow < nrows) {
            a0 = *(const float4*)(A + (size_t)grow * K + k0 + kq);
            a1 = *(const float4*)(A + (size_t)grow * K + k0 + kq + 4);
        } else {
            a0 = make_float4(0, 0, 0, 0); a1 = a0;
        }
        As[kq + 0][r] = a0.x; As[kq + 1][r] = a0.y; As[kq + 2][r] = a0.z; As[kq + 3][r] = a0.w;
        As[kq + 4][r] = a1.x; As[kq + 5][r] = a1.y; As[kq + 6][r] = a1.z; As[kq + 7][r] = a1.w;
        // splice [Wmu | Wls] rows into Ws: cols 0-63 from Wmu, 64-127 from Wls
        constexpr int WL = (BK * BN / 4) / 256;   // 4
        float4* Wsv = (float4*)Ws;
#pragma unroll
        for (int u = 0; u < WL; u++) {
            int p = tid + u * 256;          // float4 index in [0, 1024)
            int k = p >> 5;                 // row within tile (128 cols / 4 = 32 float4 per row)
            int col4 = (p & 31) * 4;        // column of this float4
            const float* src = (col4 < 64) ? (Wmu + (size_t)(k0 + k) * 64 + col4)
                                           : (Wls + (size_t)(k0 + k) * 64 + (col4 - 64));
            Wsv[p] = *(const float4*)src;
        }
        __syncthreads();
#pragma unroll
        for (int kk = 0; kk < BK; kk++) {
            float4 av0 = *(const float4*)&As[kk][trow * 8];
            float4 av1 = *(const float4*)&As[kk][trow * 8 + 4];
            float a[8] = {av0.x, av0.y, av0.z, av0.w, av1.x, av1.y, av1.z, av1.w};
            float4 bv = *(const float4*)&Ws[kk * BN + lane * 4];
            float b[4] = {bv.x, bv.y, bv.z, bv.w};
#pragma unroll
            for (int i = 0; i < 8; i++)
#pragma unroll
                for (int j = 0; j < TN; j++) acc[i][j] += a[i] * b[j];
        }
        __syncthreads();
    }

    // per-half attention vectors: lanes 0-15 use (ams, amd), lanes 16-31 use (als, ald)
    int lcol = (lane & 15) * 4;
    float sA[4], sD[4];
#pragma unroll
    for (int j = 0; j < 4; j++) {
        sA[j] = (lane < 16) ? ams[lcol + j] : als[lcol + j];
        sD[j] = (lane < 16) ? amd[lcol + j] : ald[lcol + j];
    }

#pragma unroll
    for (int i = 0; i < 8; i++) {
        int grow = row0 + trow * 8 + i;
        bool live = grow < nrows;
        if (live) {
            float4 v = make_float4(acc[i][0], acc[i][1], acc[i][2], acc[i][3]);
            *(float4*)(C + (size_t)grow * 128 + lane * 4) = v;
        }
        float ps = 0.f, pd = 0.f;
#pragma unroll
        for (int j = 0; j < 4; j++) { ps += acc[i][j] * sA[j]; pd += acc[i][j] * sD[j]; }
#pragma unroll
        for (int off = 8; off; off >>= 1) {     // half-warp reduce: stays within 16-lane halves
            ps += __shfl_xor_sync(0xffffffffu, ps, off);
            pd += __shfl_xor_sync(0xffffffffu, pd, off);
        }
        if (live) {
            if (lane == 0)  { aS[grow] = ps;  aD[grow] = pd; }
            if (lane == 16) { aS2[grow] = ps; aD2[grow] = pd; }
        }
    }
}

// ---------------- fused gather: softmax-weighted aggregation per dst ----------------
// one warp per destination node; feat rows are 128-wide; software-pipelined
// MODE 0: relu   MODE 1: relu + res
template <bool HASE, int MODE>
__global__ void __launch_bounds__(256) gather_kernel(const float* __restrict__ feat,
                                                     const float* __restrict__ bias,
                                                     const float* __restrict__ res,
                                                     float* __restrict__ out) {
    int w = blockIdx.x * 8 + (threadIdx.x >> 5);
    int lane = threadIdx.x & 31;
    if (w >= NN) return;
    int start = g_rowstart[w], end = g_rowstart[w + 1];
    float adD = g_ad[w];
    float4 acc = make_float4(0.f, 0.f, 0.f, 0.f);
    float sumex = 0.f, sumet = 0.f;

    // software pipeline: prefetch csr entry + src attention dot one iter ahead
    float4 info;
    float asv = 0.f;
    if (start < end) {
        info = g_csr[start];
        asv = g_as[__float_as_int(info.x)];
    }
    for (int j = start; j < end; j++) {
        float4 cur = info;
        float asc = asv;
        if (j + 1 < end) {
            info = g_csr[j + 1];
            asv = g_as[__float_as_int(info.x)];
        }
        int s = __float_as_int(cur.x);
        float l = asc + adD;
        if (HASE) { l += cur.y; sumet += cur.y; }
        l = l > 0.f ? l : 0.2f * l;
        float ex = __expf(l);
        const float4 v = *(const float4*)(feat + (size_t)s * 128 + lane * 4);
        acc.x += ex * v.x; acc.y += ex * v.y; acc.z += ex * v.z; acc.w += ex * v.w;
        sumex += ex;
    }
    // self-loop (attr = per-dst mean of in-edge attrs)
    float etv = HASE ? (sumet / fmaxf((float)(end - start), 1.f)) : 0.f;
    float ls = g_as[w] + adD + etv;
    ls = ls > 0.f ? ls : 0.2f * ls;
    float exs = __expf(ls);
    const float4 vd = *(const float4*)(feat + (size_t)w * 128 + lane * 4);
    acc.x += exs * vd.x; acc.y += exs * vd.y; acc.z += exs * vd.z; acc.w += exs * vd.w;
    sumex += exs;
    float inv = 1.f / (sumex + 1e-16f);
    float4 b = *(const float4*)(bias + lane * 4);
    float4 o;
    o.x = acc.x * inv + b.x; o.y = acc.y * inv + b.y;
    o.z = acc.z * inv + b.z; o.w = acc.w * inv + b.w;
    o.x = fmaxf(o.x, 0.f); o.y = fmaxf(o.y, 0.f);
    o.z = fmaxf(o.z, 0.f); o.w = fmaxf(o.w, 0.f);
    if (MODE == 1) {
        float4 r = *(const float4*)(res + (size_t)w * 128 + lane * 4);
        o.x += r.x; o.y += r.y; o.z += r.z; o.w += r.w;
    }
    *(float4*)(out + (size_t)w * 128 + lane * 4) = o;
}

// dual gather: feat rows [mu(64)|ls(64)]; lanes 0-15 mu, 16-31 ls; no activation
__global__ void __launch_bounds__(256) gather_dual_kernel(const float* __restrict__ feat,
                                                          const float* __restrict__ bmu,
                                                          const float* __restrict__ bls,
                                                          float* __restrict__ out_mu,
                                                          float* __restrict__ out_ls) {
    int w = blockIdx.x * 8 + (threadIdx.x >> 5);
    int lane = threadIdx.x & 31;
    if (w >= NN) return;
    int half = lane >> 4;                 // 0 = mu, 1 = ls
    const float* asArr = half ? g_as2 : g_as;
    float adD = half ? g_ad2[w] : g_ad[w];
    int start = g_rowstart[w], end = g_rowstart[w + 1];
    float4 acc = make_float4(0.f, 0.f, 0.f, 0.f);
    float sumex = 0.f, sumet = 0.f;

    float4 info;
    float asv = 0.f;
    if (start < end) {
        info = g_csr[start];
        asv = asArr[__float_as_int(info.x)];
    }
    for (int j = start; j < end; j++) {
        float4 cur = info;
        float asc = asv;
        if (j + 1 < end) {
            info = g_csr[j + 1];
            asv = asArr[__float_as_int(info.x)];
        }
        int s = __float_as_int(cur.x);
        float et = half ? cur.w : cur.z;
        float l = asc + adD + et;
        sumet += et;
        l = l > 0.f ? l : 0.2f * l;
        float ex = __expf(l);
        const float4 v = *(const float4*)(feat + (size_t)s * 128 + lane * 4);
        acc.x += ex * v.x; acc.y += ex * v.y; acc.z += ex * v.z; acc.w += ex * v.w;
        sumex += ex;
    }
    float etv = sumet / fmaxf((float)(end - start), 1.f);
    float ls = asArr[w] + adD + etv;
    ls = ls > 0.f ? ls : 0.2f * ls;
    float exs = __expf(ls);
    const float4 vd = *(const float4*)(feat + (size_t)w * 128 + lane * 4);
    acc.x += exs * vd.x; acc.y += exs * vd.y; acc.z += exs * vd.z; acc.w += exs * vd.w;
    sumex += exs;
    float inv = 1.f / (sumex + 1e-16f);
    int cc = (lane & 15) * 4;
    const float* bp = half ? (bls + cc) : (bmu + cc);
    float4 b = *(const float4*)bp;
    float4 o;
    o.x = acc.x * inv + b.x; o.y = acc.y * inv + b.y;
    o.z = acc.z * inv + b.z; o.w = acc.w * inv + b.w;
    float* op = half ? (out_ls + (size_t)w * 64 + cc) : (out_mu + (size_t)w * 64 + cc);
    *(float4*)op = o;
}

// ---------------- host orchestration ----------------
extern "C" void kernel_launch(void* const* d_in, const int* in_sizes, int n_in,
                              void* d_out, int out_size) {
    const float* x   = (const float*)d_in[0];
    const int*   ei  = (const int*)d_in[1];
    const float* ea  = (const float*)d_in[2];
    const float* W1  = (const float*)d_in[3];
    const float* a1s = (const float*)d_in[4];
    const float* a1d = (const float*)d_in[5];
    const float* b1  = (const float*)d_in[6];
    const float* W2  = (const float*)d_in[7];
    const float* a2s = (const float*)d_in[8];
    const float* a2d = (const float*)d_in[9];
    const float* b2  = (const float*)d_in[10];
    const float* We2 = (const float*)d_in[11];
    const float* ae2 = (const float*)d_in[12];
    const float* Wr  = (const float*)d_in[13];
    const float* br  = (const float*)d_in[14];
    const float* Wmu = (const float*)d_in[15];
    const float* ams = (const float*)d_in[16];
    const float* amd = (const float*)d_in[17];
    const float* bmu = (const float*)d_in[18];
    const float* Wem = (const float*)d_in[19];
    const float* aem = (const float*)d_in[20];
    const float* Wls = (const float*)d_in[21];
    const float* als = (const float*)d_in[22];
    const float* ald = (const float*)d_in[23];
    const float* bls = (const float*)d_in[24];
    const float* Wel = (const float*)d_in[25];
    const float* ael = (const float*)d_in[26];

    float* out_mu = (float*)d_out;
    float* out_ls = out_mu + (size_t)NN * DOUT;

    void *pFeat, *pNodeB, *pRes, *pAs, *pAd, *pAs2, *pAd2;
    cudaGetSymbolAddress(&pFeat, g_featA);
    cudaGetSymbolAddress(&pNodeB, g_nodeB);
    cudaGetSymbolAddress(&pRes, g_res);
    cudaGetSymbolAddress(&pAs, g_as);
    cudaGetSymbolAddress(&pAd, g_ad);
    cudaGetSymbolAddress(&pAs2, g_as2);
    cudaGetSymbolAddress(&pAd2, g_ad2);
    float* featA = (float*)pFeat;
    float* nodeB = (float*)pNodeB;
    float* resP  = (float*)pRes;
    float* aS  = (float*)pAs;
    float* aD  = (float*)pAd;
    float* aS2 = (float*)pAs2;
    float* aD2 = (float*)pAd2;

    const int TB = 256;
    int nbN = (NN + TB - 1) / TB;
    int nbE = (NE + TB - 1) / TB;
    int nbG = (NN + 63) / 64;
    int nbW = (NN + 7) / 8;   // gather: warp per node

    // ---- CSR build + edge-attr scalar terms ----
    zero_cnt_kernel<<<nbN, TB>>>();
    we_kernel<<<1, 64>>>(We2, ae2, Wem, aem, Wel, ael);
    count_kernel<<<nbE, TB>>>(ei);
    scan_kernel<<<1, 1024>>>();
    place_kernel<<<nbE, TB>>>(ea, ei);

    // residual (independent of edge phase)
    gemm_kernel<128><<<nbG, TB>>>(x, Wr, br, resP, NN, 128, nullptr, nullptr, nullptr, nullptr);

    // ---- conv1 (no edge attr) ----
    gemm_kernel<128><<<nbG, TB>>>(x, W1, nullptr, featA, NN, 128, a1s, a1d, aS, aD);
    gather_kernel<false, 0><<<nbW, TB>>>(featA, b1, nullptr, nodeB);

    // ---- conv2 (edge attr) + residual ----
    gemm_kernel<128><<<nbG, TB>>>(nodeB, W2, nullptr, featA, NN, 128, a2s, a2d, aS, aD);
    gather_kernel<true, 1><<<nbW, TB>>>(featA, b2, resP, nodeB);   // nodeB = h

    // ---- conv_mu + conv_logstd fused (single dual GEMM + dual gather) ----
    gemm_dual_kernel<<<nbG, TB>>>(nodeB, Wmu, Wls, featA, NN,
                                  ams, amd, als, ald, aS, aD, aS2, aD2);
    gather_dual_kernel<<<nbW, TB>>>(featA, bmu, bls, out_mu, out_ls);

    (void)in_sizes; (void)n_in; (void)out_size;
}